// round 15
// baseline (speedup 1.0000x reference)
#include <cuda_runtime.h>
#include <cstdint>

// IFS trajectory kernel — R4 structure EXACTLY (prefetch -> cp_wait<1> ->
// __syncthreads -> compute -> flush -> __syncthreads, TILE=16, NBUF=2,
// 128B half-warp-row flush, 3 blocks/SM), plus two local reductions:
//   1. full blocks (the 781/782 majority) run with no bounds checks
//   2. flush uses a pointer walk (IADD) instead of per-row IMAD chains
//
// inputs: d_in[0] = coef (BATCH, 12) f32, d_in[1] = h (ITERS, BATCH) f32
// output: (BATCH, ITERS+1, 2) f32

#define BLOCK 256
#define TILE  16
#define WARPS (BLOCK / 32)
#define NBUF  2

__device__ __forceinline__ void cp_async16(uint32_t saddr, const void* gptr) {
    asm volatile("cp.async.cg.shared.global [%0], [%1], 16;\n"
                 :: "r"(saddr), "l"(gptr));
}
__device__ __forceinline__ void cp_commit() {
    asm volatile("cp.async.commit_group;\n");
}
template <int N>
__device__ __forceinline__ void cp_wait() {
    asm volatile("cp.async.wait_group %0;\n" :: "n"(N));
}

__global__ __launch_bounds__(BLOCK, 3) void ifs_traj_kernel(
    const float* __restrict__ coef,
    const float* __restrict__ h,
    float2* __restrict__ out,
    int batch, int iters)
{
    __shared__ __align__(16) float sh[NBUF][TILE][BLOCK];   // 32 KB h ring
    __shared__ float2 so[WARPS][32][TILE + 1];              // ~35 KB staging

    const int tid  = threadIdx.x;
    const int block_b0 = blockIdx.x * BLOCK;

    // ---------------- partial last block: plain per-thread path -------------
    if (block_b0 + BLOCK > batch) {
        const int b = block_b0 + tid;
        if (b >= batch) return;
        const int stride = iters + 1;
        const float4* c4 = reinterpret_cast<const float4*>(coef + (size_t)b * 12);
        float4 ca = c4[0], cb = c4[1], cc = c4[2];
        float A0=ca.x, A1=ca.y, A2=ca.z, A3=ca.w, A4=cb.x, A5=cb.y;
        float B0=cb.z, B1=cb.w, B2=cc.x, B3=cc.y, B4=cc.z, B5=cc.w;
        float j0 = fabsf(A0*A3 - A1*A2);
        float j1 = fabsf(B0*B3 - B1*B2);
        float p = j0 / (j0 + j1);
        float x = 0.05f, y = 0.05f;
        float2* o = out + (size_t)b * stride;
        o[0] = make_float2(x, y);
        #pragma unroll 4
        for (int t = 0; t < iters; ++t) {
            float ht = __ldg(h + (size_t)t * batch + b);
            bool m = ht > p;
            float xn = fmaf(m?B0:A0, x, fmaf(m?B1:A1, y, m?B4:A4));
            float yn = fmaf(m?B2:A2, x, fmaf(m?B3:A3, y, m?B5:A5));
            x = xn; y = yn;
            o[t + 1] = make_float2(x, y);
        }
        return;
    }

    // ---------------- full blocks: checkless fast path -----------------------
    const int warp = tid >> 5;
    const int lane = tid & 31;
    const int b = block_b0 + tid;
    const int stride = iters + 1;
    const int nfull  = iters / TILE;

    float A0,A1,A2,A3,A4,A5,B0,B1,B2,B3,B4,B5,p;
    {
        const float4* c4 = reinterpret_cast<const float4*>(coef + (size_t)b * 12);
        float4 ca = c4[0], cb = c4[1], cc = c4[2];
        A0=ca.x; A1=ca.y; A2=ca.z; A3=ca.w; A4=cb.x; A5=cb.y;
        B0=cb.z; B1=cb.w; B2=cc.x; B3=cc.y; B4=cc.z; B5=cc.w;
        float j0 = fabsf(A0*A3 - A1*A2);
        float j1 = fabsf(B0*B3 - B1*B2);
        p = j0 / (j0 + j1);
        out[(size_t)b * stride] = make_float2(0.05f, 0.05f);   // initial point
    }
    float x = 0.05f, y = 0.05f;

    // ---- h-tile prefetch: 1024 float4 chunks / block, 4 per thread ----
    const uint32_t sh_base = (uint32_t)__cvta_generic_to_shared(&sh[0][0][0]);
    auto prefetch = [&](int tile, int buf) {
        const float* gbase = h + (size_t)(tile * TILE) * batch + block_b0;
        const uint32_t sbuf = sh_base + (uint32_t)(buf * TILE * BLOCK * 4);
        #pragma unroll
        for (int i = 0; i < 4; ++i) {
            int flat = tid + i * BLOCK;
            int row  = flat >> 6;              // 0..15 (64 chunks per row)
            int gb   = (flat & 63) << 2;       // float col, 16B aligned
            cp_async16(sbuf + (uint32_t)((row * BLOCK + gb) << 2),
                       gbase + (size_t)row * batch + gb);
        }
        cp_commit();
    };

    if (nfull > 0) prefetch(0, 0);

    const int rhalf = lane >> 4;     // half-warp row group
    const int ttf   = lane & 15;     // time index for flush
    // per-warp output base for the flush pointer walk (hoisted out of the loop)
    float2* const wbase = out + (size_t)(block_b0 + warp * 32 + rhalf) * stride
                        + 1 + ttf;
    const size_t step2 = 2 * (size_t)stride;   // row-pair pointer increment

    for (int tile = 0; tile < nfull; ++tile) {
        const int t0  = tile * TILE;
        const int buf = tile & 1;

        if (tile + 1 < nfull) {
            prefetch(tile + 1, buf ^ 1);       // issued BEFORE the wait (R4 order)
            cp_wait<1>();
        } else {
            cp_wait<0>();
        }
        __syncthreads();                        // h tile `tile` visible

        // ---- recurrence: 16 steps from smem, stage to per-warp slice ----
        #pragma unroll
        for (int tt = 0; tt < TILE; ++tt) {
            float ht = sh[buf][tt][tid];
            float xA = fmaf(A0, x, fmaf(A1, y, A4));
            float yA = fmaf(A2, x, fmaf(A3, y, A5));
            float xB = fmaf(B0, x, fmaf(B1, y, B4));
            float yB = fmaf(B2, x, fmaf(B3, y, B5));
            bool m = ht > p;
            x = m ? xB : xA;
            y = m ? yB : yA;
            so[warp][lane][tt] = make_float2(x, y);
        }
        __syncwarp();

        // ---- flush: half-warp writes one row's 16 float2 = 128B; pointer walk
        {
            float2* pk = wbase + t0;
            const float2* srow = &so[warp][rhalf][ttf];
            #pragma unroll
            for (int k = 0; k < 16; ++k) {
                *pk = srow[2 * k * (TILE + 1)];
                pk += step2;
            }
        }
        __syncthreads();                        // all reads of sh[buf]/so done
    }

    // ---- tail tile (iters % TILE steps) ----
    const int trem = iters - nfull * TILE;
    if (trem > 0) {
        const int t0 = nfull * TILE;
        for (int tt = 0; tt < trem; ++tt) {
            float ht = __ldg(h + (size_t)(t0 + tt) * batch + b);
            float xA = fmaf(A0, x, fmaf(A1, y, A4));
            float yA = fmaf(A2, x, fmaf(A3, y, A5));
            float xB = fmaf(B0, x, fmaf(B1, y, B4));
            float yB = fmaf(B2, x, fmaf(B3, y, B5));
            bool m = ht > p;
            x = m ? xB : xA;
            y = m ? yB : yA;
            so[warp][lane][tt] = make_float2(x, y);
        }
        __syncwarp();
        if (ttf < trem) {
            float2* pk = wbase + t0;
            const float2* srow = &so[warp][rhalf][ttf];
            #pragma unroll
            for (int k = 0; k < 16; ++k) {
                *pk = srow[2 * k * (TILE + 1)];
                pk += step2;
            }
        }
    }
}

extern "C" void kernel_launch(void* const* d_in, const int* in_sizes, int n_in,
                              void* d_out, int out_size) {
    const float* coef = (const float*)d_in[0];
    const float* h    = (const float*)d_in[1];
    float2* out       = (float2*)d_out;

    int batch = in_sizes[0] / 12;
    int iters = in_sizes[1] / batch;

    int blocks = (batch + BLOCK - 1) / BLOCK;
    ifs_traj_kernel<<<blocks, BLOCK>>>(coef, h, out, batch, iters);
}

// round 16
// speedup vs baseline: 1.0846x; 1.0846x over previous
#include <cuda_runtime.h>
#include <cstdint>

// IFS trajectory kernel, smem-tiled in time + cp.async double-buffered h.
// (Round-4 configuration — the measured optimum of this design space.)
// inputs: d_in[0] = coef (BATCH, 12) f32, d_in[1] = h (ITERS, BATCH) f32
// output: (BATCH, ITERS+1, 2) f32
//
// Per tile of TILE=16 steps:
//   prefetch tile t+1's h into smem via cp.async.cg (16B chunks) while
//   computing tile t from the other buffer; (x,y) staged per-warp in smem,
//   flushed as contiguous 128B segments per half-warp.

#define BLOCK 256
#define TILE  16
#define WARPS (BLOCK / 32)
#define NBUF  2

__device__ __forceinline__ void cp_async16(uint32_t saddr, const void* gptr) {
    asm volatile("cp.async.cg.shared.global [%0], [%1], 16;\n"
                 :: "r"(saddr), "l"(gptr));
}
__device__ __forceinline__ void cp_commit() {
    asm volatile("cp.async.commit_group;\n");
}
template <int N>
__device__ __forceinline__ void cp_wait() {
    asm volatile("cp.async.wait_group %0;\n" :: "n"(N));
}

__global__ __launch_bounds__(BLOCK, 3) void ifs_traj_kernel(
    const float* __restrict__ coef,
    const float* __restrict__ h,
    float2* __restrict__ out,
    int batch, int iters)
{
    __shared__ __align__(16) float sh[NBUF][TILE][BLOCK];   // 2 * 16KB
    __shared__ float2 so[WARPS][32][TILE + 1];              // ~35KB, +1 pad

    const int tid  = threadIdx.x;
    const int warp = tid >> 5;
    const int lane = tid & 31;
    const int block_b0 = blockIdx.x * BLOCK;
    const int b = block_b0 + tid;
    const bool active = (b < batch);
    const int stride = iters + 1;
    const int nfull = iters / TILE;

    // ---- per-element setup ----
    float A0=0,A1=0,A2=0,A3=0,A4=0,A5=0,B0=0,B1=0,B2=0,B3=0,B4=0,B5=0,p=0;
    if (active) {
        const float4* c4 = reinterpret_cast<const float4*>(coef + (size_t)b * 12);
        float4 ca = c4[0], cb = c4[1], cc = c4[2];
        A0=ca.x; A1=ca.y; A2=ca.z; A3=ca.w; A4=cb.x; A5=cb.y;
        B0=cb.z; B1=cb.w; B2=cc.x; B3=cc.y; B4=cc.z; B5=cc.w;
        float j0 = fabsf(A0*A3 - A1*A2);
        float j1 = fabsf(B0*B3 - B1*B2);
        p = j0 / (j0 + j1);
    }
    float x = 0.05f, y = 0.05f;

    // ---- h-tile prefetch: 1024 float4 chunks / block, 4 per thread ----
    auto prefetch = [&](int tile, int buf) {
        const float* gbase = h + (size_t)(tile * TILE) * batch + block_b0;
        uint32_t sbase = (uint32_t)__cvta_generic_to_shared(&sh[buf][0][0]);
        #pragma unroll
        for (int i = 0; i < 4; ++i) {
            int flat = tid + i * BLOCK;
            int row  = flat >> 6;
            int gb   = (flat & 63) << 2;
            if (block_b0 + gb < batch)   // batch % 4 == 0 assumed for alignment
                cp_async16(sbase + (uint32_t)((row * BLOCK + gb) << 2),
                           gbase + (size_t)row * batch + gb);
        }
        cp_commit();
    };

    const int warp_b0 = block_b0 + warp * 32;

    if (nfull > 0) prefetch(0, 0);

    for (int tile = 0; tile < nfull; ++tile) {
        const int t0  = tile * TILE;
        const int buf = tile & 1;

        if (tile + 1 < nfull) {
            prefetch(tile + 1, buf ^ 1);
            cp_wait<1>();
        } else {
            cp_wait<0>();
        }
        __syncthreads();   // h tile `tile` visible to all

        // ---- recurrence out of smem, stage per-warp ----
        if (active) {
            #pragma unroll
            for (int tt = 0; tt < TILE; ++tt) {
                float ht = sh[buf][tt][tid];
                float xA = fmaf(A0, x, fmaf(A1, y, A4));
                float yA = fmaf(A2, x, fmaf(A3, y, A5));
                float xB = fmaf(B0, x, fmaf(B1, y, B4));
                float yB = fmaf(B2, x, fmaf(B3, y, B5));
                bool m = ht > p;
                x = m ? xB : xA;
                y = m ? yB : yA;
                so[warp][lane][tt] = make_float2(x, y);
            }
        }
        __syncwarp();

        // ---- coalesced flush: half-warp writes one b's 16 float2 (128B) ----
        {
            const int rhalf = lane >> 4;
            const int tt    = lane & 15;
            #pragma unroll
            for (int k = 0; k < 16; ++k) {
                int bl = 2 * k + rhalf;
                int bg = warp_b0 + bl;
                if (bg < batch) {
                    size_t rowbase = (size_t)bg * stride;
                    out[rowbase + 1 + t0 + tt] = so[warp][bl][tt];
                    if (tile == 0 && tt == 0)
                        out[rowbase] = make_float2(0.05f, 0.05f); // initial point
                }
            }
        }
        __syncthreads();   // all reads of sh[buf] done before it is refilled
    }

    // ---- tail tile (iters % TILE) ----
    const int trem = iters - nfull * TILE;
    if (trem > 0) {
        const int t0 = nfull * TILE;
        if (active) {
            for (int tt = 0; tt < trem; ++tt) {
                float ht = __ldg(h + (size_t)(t0 + tt) * batch + b);
                float xA = fmaf(A0, x, fmaf(A1, y, A4));
                float yA = fmaf(A2, x, fmaf(A3, y, A5));
                float xB = fmaf(B0, x, fmaf(B1, y, B4));
                float yB = fmaf(B2, x, fmaf(B3, y, B5));
                bool m = ht > p;
                x = m ? xB : xA;
                y = m ? yB : yA;
                so[warp][lane][tt] = make_float2(x, y);
            }
        }
        __syncwarp();
        {
            const int rhalf = lane >> 4;
            const int tt    = lane & 15;
            for (int k = 0; k < 16; ++k) {
                int bl = 2 * k + rhalf;
                int bg = warp_b0 + bl;
                if (bg < batch && tt < trem)
                    out[(size_t)bg * stride + 1 + t0 + tt] = so[warp][bl][tt];
            }
        }
    }
}

extern "C" void kernel_launch(void* const* d_in, const int* in_sizes, int n_in,
                              void* d_out, int out_size) {
    const float* coef = (const float*)d_in[0];
    const float* h    = (const float*)d_in[1];
    float2* out       = (float2*)d_out;

    int batch = in_sizes[0] / 12;
    int iters = in_sizes[1] / batch;

    int blocks = (batch + BLOCK - 1) / BLOCK;
    ifs_traj_kernel<<<blocks, BLOCK>>>(coef, h, out, batch, iters);
}